// round 4
// baseline (speedup 1.0000x reference)
#include <cuda_runtime.h>
#include <math.h>

#define BB 8
#define PP 4096
#define CC 91
#define CM1 90
#define FD 1024
#define DETS 100
#define ROWCAP 512
#define CANDCAP 1024
#define BBOX_CLIP 4.135166556742356f
#define IMGF 800.0f
#define RT 64                       // rows per block in rowmax_k

__device__ unsigned int g_rowmax[BB * PP];
__device__ int g_keptp[BB * DETS];

// ---------------------------------------------------------------------------
// K1: 2 threads per row, 64 rows/block (grid=512). Stage 64 rows (23.3 KB)
// coalesced via float4, then single streaming pass: sum of __expf(logit) over
// all 91 classes (no max-subtract needed: |logit|<~6 so no overflow) and max
// logit over classes 1..90. score = __expf(maxlogit)/sum.
// ---------------------------------------------------------------------------
__global__ void __launch_bounds__(128) rowmax_k(const float* __restrict__ logits) {
    __shared__ float s[RT * CC];               // 23296 bytes
    int tid = threadIdx.x;
    const float4* src = (const float4*)(logits + (size_t)blockIdx.x * RT * CC);
    float4* dst = (float4*)s;
    for (int i = tid; i < RT * CC / 4; i += 128) dst[i] = src[i];   // 1456 vec4
    __syncthreads();

    int row = tid >> 1, sub = tid & 1;
    const float* r = s + row * CC + sub * 46;  // sub0: cols 0..45, sub1: cols 46..90
    int n = 46 - sub;

    float s0 = 0.f, s1 = 0.f, s2 = 0.f;
    float a0 = -1e30f, a1 = -1e30f, a2 = -1e30f;
    int j = 0;
    if (sub == 0) { s0 = __expf(r[0]); j = 1; }  // class 0: in sum, not in max
    for (; j + 2 < n; j += 3) {
        float v0 = r[j], v1 = r[j + 1], v2 = r[j + 2];
        s0 += __expf(v0); s1 += __expf(v1); s2 += __expf(v2);
        a0 = fmaxf(a0, v0); a1 = fmaxf(a1, v1); a2 = fmaxf(a2, v2);
    }
    for (; j < n; j++) {
        float v = r[j];
        s0 += __expf(v);
        a0 = fmaxf(a0, v);
    }
    float sum = s0 + s1 + s2;
    float m1 = fmaxf(a0, fmaxf(a1, a2));

    sum += __shfl_xor_sync(0xffffffffu, sum, 1);
    m1 = fmaxf(m1, __shfl_xor_sync(0xffffffffu, m1, 1));

    if (sub == 0)
        g_rowmax[blockIdx.x * RT + row] = __float_as_uint(__expf(m1) / sum);
}

// ---------------------------------------------------------------------------
// Warp-parallel descending threshold search over 256-bin histogram.
// ---------------------------------------------------------------------------
__device__ __forceinline__ void find_thresh(const int* h, int need, int* s_b, int* s_cum) {
    int L = threadIdx.x;              // tid < 32 only
    int hi = 255 - 8 * L;
    int hb[8], cs = 0;
    #pragma unroll
    for (int j = 0; j < 8; j++) { hb[j] = h[hi - j]; cs += hb[j]; }
    int pref = cs;
    #pragma unroll
    for (int o = 1; o < 32; o <<= 1) {
        int t = __shfl_up_sync(0xffffffffu, pref, o);
        if (L >= o) pref += t;
    }
    int above = pref - cs;
    if (above < need && need <= pref) {
        int cum = above;
        #pragma unroll
        for (int j = 0; j < 8; j++) {
            if (cum + hb[j] >= need) { *s_b = hi - j; *s_cum = cum; break; }
            cum += hb[j];
        }
    }
}

// ---------------------------------------------------------------------------
// K2: one block (1024 threads) per image. 2-level radix threshold on approx
// rowmaxes (with margins), compact rows, exact re-softmax, exact top-100 by
// rank-counting on (score_bits<<32)|~idx keys, decode+clip+scale boxes.
// ---------------------------------------------------------------------------
__global__ void __launch_bounds__(1024, 1) select_k(const float* __restrict__ logits,
                                                    const float* __restrict__ reg,
                                                    const float* __restrict__ props,
                                                    float* __restrict__ out) {
    __shared__ unsigned vals[PP];
    __shared__ int h[256];
    __shared__ int rowbuf[ROWCAP];
    __shared__ unsigned long long cand[CANDCAP];
    __shared__ int s_nrows, s_ncand, s_b1, s_cumAbove, s_fb, s_fcum;

    int img = blockIdx.x;
    int tid = threadIdx.x;
    int lane = tid & 31;

    for (int i = tid; i < PP; i += 1024) vals[i] = g_rowmax[img * PP + i];
    if (tid < 256) h[tid] = 0;
    if (tid == 0) { s_nrows = 0; s_ncand = 0; }
    __syncthreads();
    for (int i = tid; i < PP; i += 1024) {
        int bin = vals[i] >> 22;
        unsigned peers = __match_any_sync(0xffffffffu, bin);
        if (lane == __ffs(peers) - 1) atomicAdd(&h[bin], __popc(peers));
    }
    __syncthreads();
    if (tid < 32) find_thresh(h, DETS, &s_b1, &s_cumAbove);
    __syncthreads();
    int b1 = s_b1;

    if (tid < 256) h[tid] = 0;
    __syncthreads();
    for (int i = tid; i < PP; i += 1024) {
        unsigned v = vals[i];
        bool pred = ((int)(v >> 22) == b1);
        unsigned active = __ballot_sync(0xffffffffu, pred);
        if (pred) {
            int bin = (v >> 14) & 0xFF;
            unsigned peers = __match_any_sync(active, bin);
            if (lane == __ffs(peers) - 1) atomicAdd(&h[bin], __popc(peers));
        }
    }
    __syncthreads();
    if (tid < 32) find_thresh(h, DETS - s_cumAbove, &s_fb, &s_fcum);
    __syncthreads();
    unsigned T = ((unsigned)b1 << 8) | (unsigned)s_fb;
    unsigned Tc = (T >= 2) ? T - 2 : 0;   // row compaction threshold (approx margin)
    unsigned Te = (T >= 1) ? T - 1 : 0;   // candidate emission threshold

    for (int i = tid; i < PP; i += 1024) {
        bool keep = (vals[i] >> 14) >= Tc;
        unsigned b = __ballot_sync(0xffffffffu, keep);
        int cnt = __popc(b);
        if (cnt) {
            int basepos = 0;
            if (lane == 0) basepos = atomicAdd(&s_nrows, cnt);
            basepos = __shfl_sync(0xffffffffu, basepos, 0);
            if (keep) {
                int pos = basepos + __popc(b & ((1u << lane) - 1));
                if (pos < ROWCAP) rowbuf[pos] = i;
            }
        }
    }
    __syncthreads();
    int nrows = min(s_nrows, ROWCAP);

    int warp = tid >> 5;
    for (int r = warp; r < nrows; r += 32) {
        int p = rowbuf[r];
        const float* l = logits + (size_t)(img * PP + p) * CC;
        float v0 = l[lane];
        float v1 = l[lane + 32];
        float v2 = (lane < 27) ? l[lane + 64] : -1e30f;
        float m = fmaxf(v0, fmaxf(v1, v2));
        #pragma unroll
        for (int o = 16; o; o >>= 1) m = fmaxf(m, __shfl_xor_sync(0xffffffffu, m, o));
        float e0 = expf(v0 - m);
        float e1 = expf(v1 - m);
        float e2 = (lane < 27) ? expf(v2 - m) : 0.0f;
        float s = e0 + e1 + e2;
        #pragma unroll
        for (int o = 16; o; o >>= 1) s += __shfl_xor_sync(0xffffffffu, s, o);

        unsigned base = (unsigned)p * CM1;
        if (lane > 0) {
            unsigned b = __float_as_uint(e0 / s);
            if ((b >> 14) >= Te) {
                int pos = atomicAdd(&s_ncand, 1);
                if (pos < CANDCAP)
                    cand[pos] = (((unsigned long long)b) << 32) | (unsigned)(~(base + lane - 1));
            }
        }
        {
            unsigned b = __float_as_uint(e1 / s);
            if ((b >> 14) >= Te) {
                int pos = atomicAdd(&s_ncand, 1);
                if (pos < CANDCAP)
                    cand[pos] = (((unsigned long long)b) << 32) | (unsigned)(~(base + lane + 31));
            }
        }
        if (lane < 27) {
            unsigned b = __float_as_uint(e2 / s);
            if ((b >> 14) >= Te) {
                int pos = atomicAdd(&s_ncand, 1);
                if (pos < CANDCAP)
                    cand[pos] = (((unsigned long long)b) << 32) | (unsigned)(~(base + lane + 63));
            }
        }
    }
    __syncthreads();

    int nc = min(s_ncand, CANDCAP);
    if (tid < nc) {
        unsigned long long my = cand[tid];
        int rank = 0;
        for (int j = 0; j < nc; j++) rank += (cand[j] > my);
        if (rank < DETS) {
            unsigned idxl = ~(unsigned)(my & 0xFFFFFFFFull);
            int p = idxl / CM1;
            int c = idxl - p * CM1 + 1;

            const float* pr = props + ((size_t)img * PP + p) * 4;
            float x1 = pr[0], y1 = pr[1], x2 = pr[2], y2 = pr[3];
            float w = x2 - x1, hh = y2 - y1;
            float cx = x1 + 0.5f * w, cy = y1 + 0.5f * hh;

            const float* rg = reg + ((size_t)img * PP + p) * (4 * CC) + 4 * c;
            float dx = rg[0] / 10.0f;
            float dy = rg[1] / 10.0f;
            float dw = fminf(rg[2] / 5.0f, BBOX_CLIP);
            float dh = fminf(rg[3] / 5.0f, BBOX_CLIP);

            float pcx = dx * w + cx, pcy = dy * hh + cy;
            float pw = expf(dw) * w, ph = expf(dh) * hh;

            float bx1 = fminf(fmaxf(pcx - 0.5f * pw, 0.0f), IMGF);
            float by1 = fminf(fmaxf(pcy - 0.5f * ph, 0.0f), IMGF);
            float bx2 = fminf(fmaxf(pcx + 0.5f * pw, 0.0f), IMGF);
            float by2 = fminf(fmaxf(pcy + 0.5f * ph, 0.0f), IMGF);

            float* ob = out + ((size_t)img * DETS + rank) * 4;
            ob[0] = bx1 / IMGF;
            ob[1] = by1 / IMGF;
            ob[2] = bx2 / IMGF;
            ob[3] = by2 / IMGF;
            g_keptp[img * DETS + rank] = p;
        }
    }
}

// ---------------------------------------------------------------------------
// K3: feature gather, one block per detection, float4 vectorized
// ---------------------------------------------------------------------------
__global__ void gather_k(const float* __restrict__ feats, float* __restrict__ out) {
    int img = blockIdx.x / DETS;
    int p = g_keptp[blockIdx.x];
    const float4* src = (const float4*)(feats + ((size_t)img * PP + p) * FD);
    float4* dst = (float4*)(out + BB * DETS * 4 + (size_t)blockIdx.x * FD);
    dst[threadIdx.x] = src[threadIdx.x];
}

extern "C" void kernel_launch(void* const* d_in, const int* in_sizes, int n_in,
                              void* d_out, int out_size) {
    const float* logits = (const float*)d_in[0];
    const float* reg    = (const float*)d_in[1];
    const float* props  = (const float*)d_in[2];
    const float* feats  = (const float*)d_in[3];
    float* out = (float*)d_out;

    rowmax_k<<<BB * PP / RT, 128>>>(logits);
    select_k<<<BB, 1024>>>(logits, reg, props, out);
    gather_k<<<BB * DETS, 256>>>(feats, out);
}

// round 5
// speedup vs baseline: 1.1099x; 1.1099x over previous
#include <cuda_runtime.h>
#include <math.h>

#define BB 8
#define PP 4096
#define CC 91
#define CM1 90
#define FD 1024
#define DETS 100
#define ROWCAP 512
#define CANDCAP 1024
#define BBOX_CLIP 4.135166556742356f
#define IMGF 800.0f
#define RT 64                       // rows per block in rowmax_k

__device__ unsigned int g_rowmax[BB * PP];
__device__ int g_keptp[BB * DETS];

// ---------------------------------------------------------------------------
// K1: 4 threads per row, 64 rows/block, 256 threads (grid=512, 8 warps/blk).
// Stage 64 rows (23.3 KB) coalesced via float4, then one fully-unrolled pass
// per 23-element chunk: sum of __expf(logit) over all classes (|logit|<~6,
// no overflow) and max logit over classes 1..90. score = __expf(m1)/sum.
// Compile-time trip count (23) keeps full ILP (~23 independent MUFU ops).
// ---------------------------------------------------------------------------
__global__ void __launch_bounds__(256) rowmax_k(const float* __restrict__ logits) {
    __shared__ float s[RT * CC];               // 23296 bytes
    int tid = threadIdx.x;
    const float4* src = (const float4*)(logits + (size_t)blockIdx.x * RT * CC);
    float4* dst = (float4*)s;
    #pragma unroll
    for (int k = 0; k < 6; k++) {
        int i = tid + k * 256;
        if (i < RT * CC / 4) dst[i] = src[i];  // 1456 vec4, MLP~6
    }
    __syncthreads();

    int row = tid >> 2, sub = tid & 3;
    const float* r = s + row * CC;
    int base = sub * 23;                       // sub3 covers 69..90 (22 real)

    float s0 = 0.f, s1 = 0.f, s2 = 0.f, s3 = 0.f;
    float a0 = -1e30f, a1 = -1e30f, a2 = -1e30f, a3 = -1e30f;
    #pragma unroll
    for (int j = 0; j < 23; j += 4) {
        #pragma unroll
        for (int q = 0; q < 4; q++) {
            int jj = j + q;
            if (jj < 23) {
                int idx = base + jj;
                float v = (idx < CC) ? r[idx] : -1e30f;     // pad -> exp 0
                float vm = (idx > 0) ? v : -1e30f;          // class 0 not in max
                if (q == 0) { s0 += __expf(v); a0 = fmaxf(a0, vm); }
                if (q == 1) { s1 += __expf(v); a1 = fmaxf(a1, vm); }
                if (q == 2) { s2 += __expf(v); a2 = fmaxf(a2, vm); }
                if (q == 3) { s3 += __expf(v); a3 = fmaxf(a3, vm); }
            }
        }
    }
    float sum = (s0 + s1) + (s2 + s3);
    float m1 = fmaxf(fmaxf(a0, a1), fmaxf(a2, a3));

    sum += __shfl_xor_sync(0xffffffffu, sum, 1);
    sum += __shfl_xor_sync(0xffffffffu, sum, 2);
    m1 = fmaxf(m1, __shfl_xor_sync(0xffffffffu, m1, 1));
    m1 = fmaxf(m1, __shfl_xor_sync(0xffffffffu, m1, 2));

    if (sub == 0)
        g_rowmax[blockIdx.x * RT + row] = __float_as_uint(__expf(m1) / sum);
}

// ---------------------------------------------------------------------------
// Warp-parallel descending threshold search over 256-bin histogram.
// ---------------------------------------------------------------------------
__device__ __forceinline__ void find_thresh(const int* h, int need, int* s_b, int* s_cum) {
    int L = threadIdx.x;              // tid < 32 only
    int hi = 255 - 8 * L;
    int hb[8], cs = 0;
    #pragma unroll
    for (int j = 0; j < 8; j++) { hb[j] = h[hi - j]; cs += hb[j]; }
    int pref = cs;
    #pragma unroll
    for (int o = 1; o < 32; o <<= 1) {
        int t = __shfl_up_sync(0xffffffffu, pref, o);
        if (L >= o) pref += t;
    }
    int above = pref - cs;
    if (above < need && need <= pref) {
        int cum = above;
        #pragma unroll
        for (int j = 0; j < 8; j++) {
            if (cum + hb[j] >= need) { *s_b = hi - j; *s_cum = cum; break; }
            cum += hb[j];
        }
    }
}

// ---------------------------------------------------------------------------
// K2: one block (1024 threads) per image. 2-level radix threshold on approx
// rowmaxes (with margins), compact rows, exact re-softmax, exact top-100 by
// rank-counting on (score_bits<<32)|~idx keys, decode+clip+scale boxes.
// ---------------------------------------------------------------------------
__global__ void __launch_bounds__(1024, 1) select_k(const float* __restrict__ logits,
                                                    const float* __restrict__ reg,
                                                    const float* __restrict__ props,
                                                    float* __restrict__ out) {
    __shared__ unsigned vals[PP];
    __shared__ int h[256];
    __shared__ int rowbuf[ROWCAP];
    __shared__ unsigned long long cand[CANDCAP];
    __shared__ int s_nrows, s_ncand, s_b1, s_cumAbove, s_fb, s_fcum;

    int img = blockIdx.x;
    int tid = threadIdx.x;
    int lane = tid & 31;

    for (int i = tid; i < PP; i += 1024) vals[i] = g_rowmax[img * PP + i];
    if (tid < 256) h[tid] = 0;
    if (tid == 0) { s_nrows = 0; s_ncand = 0; }
    __syncthreads();
    for (int i = tid; i < PP; i += 1024) {
        int bin = vals[i] >> 22;
        unsigned peers = __match_any_sync(0xffffffffu, bin);
        if (lane == __ffs(peers) - 1) atomicAdd(&h[bin], __popc(peers));
    }
    __syncthreads();
    if (tid < 32) find_thresh(h, DETS, &s_b1, &s_cumAbove);
    __syncthreads();
    int b1 = s_b1;

    if (tid < 256) h[tid] = 0;
    __syncthreads();
    for (int i = tid; i < PP; i += 1024) {
        unsigned v = vals[i];
        bool pred = ((int)(v >> 22) == b1);
        unsigned active = __ballot_sync(0xffffffffu, pred);
        if (pred) {
            int bin = (v >> 14) & 0xFF;
            unsigned peers = __match_any_sync(active, bin);
            if (lane == __ffs(peers) - 1) atomicAdd(&h[bin], __popc(peers));
        }
    }
    __syncthreads();
    if (tid < 32) find_thresh(h, DETS - s_cumAbove, &s_fb, &s_fcum);
    __syncthreads();
    unsigned T = ((unsigned)b1 << 8) | (unsigned)s_fb;
    unsigned Tc = (T >= 2) ? T - 2 : 0;   // row compaction threshold (approx margin)
    unsigned Te = (T >= 1) ? T - 1 : 0;   // candidate emission threshold

    for (int i = tid; i < PP; i += 1024) {
        bool keep = (vals[i] >> 14) >= Tc;
        unsigned b = __ballot_sync(0xffffffffu, keep);
        int cnt = __popc(b);
        if (cnt) {
            int basepos = 0;
            if (lane == 0) basepos = atomicAdd(&s_nrows, cnt);
            basepos = __shfl_sync(0xffffffffu, basepos, 0);
            if (keep) {
                int pos = basepos + __popc(b & ((1u << lane) - 1));
                if (pos < ROWCAP) rowbuf[pos] = i;
            }
        }
    }
    __syncthreads();
    int nrows = min(s_nrows, ROWCAP);

    int warp = tid >> 5;
    for (int r = warp; r < nrows; r += 32) {
        int p = rowbuf[r];
        const float* l = logits + (size_t)(img * PP + p) * CC;
        float v0 = l[lane];
        float v1 = l[lane + 32];
        float v2 = (lane < 27) ? l[lane + 64] : -1e30f;
        float m = fmaxf(v0, fmaxf(v1, v2));
        #pragma unroll
        for (int o = 16; o; o >>= 1) m = fmaxf(m, __shfl_xor_sync(0xffffffffu, m, o));
        float e0 = expf(v0 - m);
        float e1 = expf(v1 - m);
        float e2 = (lane < 27) ? expf(v2 - m) : 0.0f;
        float s = e0 + e1 + e2;
        #pragma unroll
        for (int o = 16; o; o >>= 1) s += __shfl_xor_sync(0xffffffffu, s, o);

        unsigned base = (unsigned)p * CM1;
        if (lane > 0) {
            unsigned b = __float_as_uint(e0 / s);
            if ((b >> 14) >= Te) {
                int pos = atomicAdd(&s_ncand, 1);
                if (pos < CANDCAP)
                    cand[pos] = (((unsigned long long)b) << 32) | (unsigned)(~(base + lane - 1));
            }
        }
        {
            unsigned b = __float_as_uint(e1 / s);
            if ((b >> 14) >= Te) {
                int pos = atomicAdd(&s_ncand, 1);
                if (pos < CANDCAP)
                    cand[pos] = (((unsigned long long)b) << 32) | (unsigned)(~(base + lane + 31));
            }
        }
        if (lane < 27) {
            unsigned b = __float_as_uint(e2 / s);
            if ((b >> 14) >= Te) {
                int pos = atomicAdd(&s_ncand, 1);
                if (pos < CANDCAP)
                    cand[pos] = (((unsigned long long)b) << 32) | (unsigned)(~(base + lane + 63));
            }
        }
    }
    __syncthreads();

    int nc = min(s_ncand, CANDCAP);
    if (tid < nc) {
        unsigned long long my = cand[tid];
        int rank = 0;
        for (int j = 0; j < nc; j++) rank += (cand[j] > my);
        if (rank < DETS) {
            unsigned idxl = ~(unsigned)(my & 0xFFFFFFFFull);
            int p = idxl / CM1;
            int c = idxl - p * CM1 + 1;

            const float* pr = props + ((size_t)img * PP + p) * 4;
            float x1 = pr[0], y1 = pr[1], x2 = pr[2], y2 = pr[3];
            float w = x2 - x1, hh = y2 - y1;
            float cx = x1 + 0.5f * w, cy = y1 + 0.5f * hh;

            const float* rg = reg + ((size_t)img * PP + p) * (4 * CC) + 4 * c;
            float dx = rg[0] / 10.0f;
            float dy = rg[1] / 10.0f;
            float dw = fminf(rg[2] / 5.0f, BBOX_CLIP);
            float dh = fminf(rg[3] / 5.0f, BBOX_CLIP);

            float pcx = dx * w + cx, pcy = dy * hh + cy;
            float pw = expf(dw) * w, ph = expf(dh) * hh;

            float bx1 = fminf(fmaxf(pcx - 0.5f * pw, 0.0f), IMGF);
            float by1 = fminf(fmaxf(pcy - 0.5f * ph, 0.0f), IMGF);
            float bx2 = fminf(fmaxf(pcx + 0.5f * pw, 0.0f), IMGF);
            float by2 = fminf(fmaxf(pcy + 0.5f * ph, 0.0f), IMGF);

            float* ob = out + ((size_t)img * DETS + rank) * 4;
            ob[0] = bx1 / IMGF;
            ob[1] = by1 / IMGF;
            ob[2] = bx2 / IMGF;
            ob[3] = by2 / IMGF;
            g_keptp[img * DETS + rank] = p;
        }
    }
}

// ---------------------------------------------------------------------------
// K3: feature gather, one block per detection, float4 vectorized
// ---------------------------------------------------------------------------
__global__ void gather_k(const float* __restrict__ feats, float* __restrict__ out) {
    int img = blockIdx.x / DETS;
    int p = g_keptp[blockIdx.x];
    const float4* src = (const float4*)(feats + ((size_t)img * PP + p) * FD);
    float4* dst = (float4*)(out + BB * DETS * 4 + (size_t)blockIdx.x * FD);
    dst[threadIdx.x] = src[threadIdx.x];
}

extern "C" void kernel_launch(void* const* d_in, const int* in_sizes, int n_in,
                              void* d_out, int out_size) {
    const float* logits = (const float*)d_in[0];
    const float* reg    = (const float*)d_in[1];
    const float* props  = (const float*)d_in[2];
    const float* feats  = (const float*)d_in[3];
    float* out = (float*)d_out;

    rowmax_k<<<BB * PP / RT, 256>>>(logits);
    select_k<<<BB, 1024>>>(logits, reg, props, out);
    gather_k<<<BB * DETS, 256>>>(feats, out);
}